// round 3
// baseline (speedup 1.0000x reference)
#include <cuda_runtime.h>
#include <cuda_bf16.h>
#include <cstddef>

// Problem constants
#define BB    2
#define NN    207
#define TT    12
#define FIN   64
#define HH    8
#define CDIM  8
#define NPAD  208
#define NWORDS 7            // ceil(207/32)
#define NCHUNK 3
#define RPC   69            // rows per chunk: 207 = 3*69
#define NROWS (BB*NN*TT)    // 4968 rows of X

// Scratch (no allocation allowed -> __device__ globals)
__device__ float    g_h[BB*TT*HH*NN*CDIM];   // layout: [((b*T+t)*H+hd)][n][c]
__device__ unsigned g_mask[NN*NWORDS];       // bitmask of A_hat>0, bit m%32 of word m/32

// ---------------------------------------------------------------------------
// Kernel 0: adjacency bitmask. grid = NN, block = 224 (7 warps).
// ---------------------------------------------------------------------------
__global__ void k_mask(const float* __restrict__ A) {
    int n = blockIdx.x;
    int m = threadIdx.x;
    bool v = false;
    if (m < NN) v = A[n * NN + m] > 0.0f;
    unsigned bits = __ballot_sync(0xffffffffu, v);
    if ((threadIdx.x & 31) == 0)
        g_mask[n * NWORDS + (threadIdx.x >> 5)] = bits;
}

// ---------------------------------------------------------------------------
// Kernel 1: h = X @ W, scattered into (b,t,head)-major layout.
// grid = ceil(4968/4), block = 256 (4 rows x 64 output cols).
// ---------------------------------------------------------------------------
__global__ void k_gemm(const float* __restrict__ X, const float* __restrict__ W) {
    __shared__ float xs[4][FIN];
    int lr  = threadIdx.x >> 6;        // local row 0..3
    int j   = threadIdx.x & 63;        // output column 0..63
    int row = blockIdx.x * 4 + lr;
    if (row < NROWS) xs[lr][j] = X[row * FIN + j];
    __syncthreads();
    if (row >= NROWS) return;

    float acc = 0.0f;
#pragma unroll
    for (int f = 0; f < FIN; f++)
        acc = fmaf(xs[lr][f], W[f * 64 + j], acc);

    int b   = row / (NN * TT);
    int rem = row - b * (NN * TT);
    int n   = rem / TT;
    int t   = rem - n * TT;
    int hd  = j >> 3;
    int c   = j & 7;
    g_h[(((size_t)((b * TT + t) * HH + hd)) * NN + n) * CDIM + c] = acc;
}

// ---------------------------------------------------------------------------
// Kernel 2: masked softmax diagonal + scale.
// e[n,m] = p_n + p_m + sum_c a4_c * |h_n_c + h_m_c|   (leaky = 0.6x + 0.4|x|)
// grid = B*T*H*NCHUNK = 576, block = 256 (8 warps, 1 row per warp per iter).
// ---------------------------------------------------------------------------
__global__ void __launch_bounds__(256) k_att(const float* __restrict__ a_vec,
                                             float* __restrict__ out) {
    __shared__ float    h_sh[CDIM * NPAD];   // transposed: h_sh[c*NPAD + m]
    __shared__ float    p_sh[NPAD];
    __shared__ unsigned msk[RPC * NWORDS];

    int bx    = blockIdx.x;
    int bth   = bx / NCHUNK;                 // 0..191 == (b*T+t)*H + hd
    int chunk = bx - bth * NCHUNK;
    int hd    = bth & 7;
    int bt    = bth >> 3;                    // b*T + t
    int t     = bt % TT;
    int b     = bt / TT;
    int tid   = threadIdx.x;

    float a6[CDIM], a4[CDIM];
#pragma unroll
    for (int c = 0; c < CDIM; c++) {
        float av = __ldg(&a_vec[c]);
        a6[c] = 0.6f * av;
        a4[c] = 0.4f * av;
    }

    // Load h slab (transposed) + mask rows for this chunk.
    const float* hg = g_h + (size_t)bth * NN * CDIM;
    for (int i = tid; i < NN * CDIM; i += 256) {
        int n = i >> 3, c = i & 7;
        h_sh[c * NPAD + n] = hg[i];
    }
    int n0 = chunk * RPC;
    for (int i = tid; i < RPC * NWORDS; i += 256)
        msk[i] = g_mask[n0 * NWORDS + i];
    __syncthreads();

    // p_m = sum_c 0.6*a_c*h_m_c
    if (tid < NN) {
        float p = 0.0f;
#pragma unroll
        for (int c = 0; c < CDIM; c++)
            p = fmaf(a6[c], h_sh[c * NPAD + tid], p);
        p_sh[tid] = p;
    }
    __syncthreads();

    int warp = tid >> 5, lane = tid & 31;

    for (int nl = warp; nl < RPC; nl += 8) {
        int n = n0 + nl;
        float hn[CDIM];
#pragma unroll
        for (int c = 0; c < CDIM; c++) hn[c] = h_sh[c * NPAD + n];
        float pn = p_sh[n];

        float e[NWORDS];
#pragma unroll
        for (int k = 0; k < NWORDS; k++) {
            int m  = k * 32 + lane;
            int mm = min(m, NN - 1);               // clamp shared reads
            unsigned bits = msk[nl * NWORDS + k];  // broadcast; bits>=207 are 0
            float s0 = 0.0f, s1 = 0.0f;
#pragma unroll
            for (int c = 0; c < CDIM; c++) {
                float x = hn[c] + h_sh[c * NPAD + mm];
                if (c & 1) s1 = fmaf(a4[c], fabsf(x), s1);
                else       s0 = fmaf(a4[c], fabsf(x), s0);
            }
            float ev = pn + p_sh[mm] + (s0 + s1);
            e[k] = ((bits >> lane) & 1u) ? ev : -1e30f;
        }

        // row max
        float mx = e[0];
#pragma unroll
        for (int k = 1; k < NWORDS; k++) mx = fmaxf(mx, e[k]);
#pragma unroll
        for (int off = 16; off; off >>= 1)
            mx = fmaxf(mx, __shfl_xor_sync(0xffffffffu, mx, off));

        // normalizer
        float s = 0.0f;
#pragma unroll
        for (int k = 0; k < NWORDS; k++) s += __expf(e[k] - mx);
#pragma unroll
        for (int off = 16; off; off >>= 1)
            s += __shfl_xor_sync(0xffffffffu, s, off);

        // diagonal attention weight (warp-uniform branch)
        unsigned dbits = msk[nl * NWORDS + (n >> 5)];
        float att = 0.0f;
        if ((dbits >> (n & 31)) & 1u) {
            float d0 = 0.0f;
#pragma unroll
            for (int c = 0; c < CDIM; c++) d0 = fmaf(a4[c], fabsf(hn[c]), d0);
            float enn = 2.0f * (pn + d0);          // e[n,n]
            att = __expf(enn - mx) / s;
        }

        // out[b][n][t][hd*8+c] = att * h
        if (lane < CDIM) {
            float hv = h_sh[lane * NPAD + n];
            out[((size_t)(b * NN + n) * TT + t) * (HH * CDIM) + hd * CDIM + lane] = att * hv;
        }
    }
}

// ---------------------------------------------------------------------------
extern "C" void kernel_launch(void* const* d_in, const int* in_sizes, int n_in,
                              void* d_out, int out_size) {
    const float* X  = (const float*)d_in[0];   // (2,207,12,64)
    const float* A  = (const float*)d_in[1];   // (207,207)
    const float* W  = (const float*)d_in[2];   // (64,64)
    const float* av = (const float*)d_in[3];   // (8,)
    float* out = (float*)d_out;                // (2,207,12,64)

    k_mask<<<NN, 224>>>(A);
    k_gemm<<<(NROWS + 3) / 4, 256>>>(X, W);
    k_att<<<BB * TT * HH * NCHUNK, 256>>>(av, out);
}

// round 4
// speedup vs baseline: 1.0446x; 1.0446x over previous
#include <cuda_runtime.h>
#include <cstddef>

#define BB    2
#define NN    207
#define TT    12
#define FIN   64
#define HH    8
#define CDIM  8
#define NPAD  208
#define NWORDS 7          // ceil(207/32)
#define NCHUNK 3
#define RPC   69          // rows per chunk: 207 = 3*69
#define NGRP  35          // ceil(69/2) row-pair groups per chunk
#define NEG   (-1e30f)

// ---------------------------------------------------------------------------
// Single fused kernel: per-block GEMM (h slab for one (b,t,head)) + masked
// softmax diagonal + scale. grid = B*T*H*NCHUNK = 576, block = 256.
// e[n,m] = p_n + p_m + sum_c 0.4*a_c*|h_n_c + h_m_c|   (leaky = 0.6x + 0.4|x|)
// ---------------------------------------------------------------------------
__global__ void __launch_bounds__(256) k_fused(
    const float* __restrict__ X, const float* __restrict__ A,
    const float* __restrict__ W, const float* __restrict__ a_vec,
    float* __restrict__ out)
{
    __shared__ float h_sh[CDIM * NPAD];   // transposed: h_sh[c*NPAD + m]
    __shared__ float p_sh[NPAD];
    __shared__ float ws[FIN * CDIM];      // W column block for this head

    int bx    = blockIdx.x;
    int bth   = bx / NCHUNK;              // (b*T+t)*H + hd
    int chunk = bx - bth * NCHUNK;
    int hd    = bth & 7;
    int bt    = bth >> 3;
    int t     = bt % TT;
    int b     = bt / TT;
    int tid   = threadIdx.x;
    int warp  = tid >> 5, lane = tid & 31;

    float a4[CDIM];
#pragma unroll
    for (int c = 0; c < CDIM; c++) a4[c] = 0.4f * __ldg(&a_vec[c]);

    // Stage W[:, hd*8 .. hd*8+7] into shared (64x8 floats).
    if (tid < 128) {
        int f = tid >> 1, half = tid & 1;
        *(float4*)&ws[f * CDIM + half * 4] =
            *(const float4*)&W[f * 64 + hd * CDIM + half * 4];
    }
    __syncthreads();

    // Per-block GEMM: thread n computes h[n][0..7] for this (b,t,head).
    if (tid < NN) {
        int n = tid;
        const float* xr = X + ((size_t)(b * NN + n) * TT + t) * FIN;
        float acc[CDIM];
#pragma unroll
        for (int c = 0; c < CDIM; c++) acc[c] = 0.0f;
#pragma unroll
        for (int f = 0; f < FIN; f += 4) {
            float4 xv = *(const float4*)(xr + f);
            float xs4[4] = {xv.x, xv.y, xv.z, xv.w};
#pragma unroll
            for (int ff = 0; ff < 4; ff++) {
                float xs = xs4[ff];
                float4 w0 = *(float4*)&ws[(f + ff) * CDIM];
                float4 w1 = *(float4*)&ws[(f + ff) * CDIM + 4];
                acc[0] = fmaf(xs, w0.x, acc[0]);
                acc[1] = fmaf(xs, w0.y, acc[1]);
                acc[2] = fmaf(xs, w0.z, acc[2]);
                acc[3] = fmaf(xs, w0.w, acc[3]);
                acc[4] = fmaf(xs, w1.x, acc[4]);
                acc[5] = fmaf(xs, w1.y, acc[5]);
                acc[6] = fmaf(xs, w1.z, acc[6]);
                acc[7] = fmaf(xs, w1.w, acc[7]);
            }
        }
        float p = 0.0f;
#pragma unroll
        for (int c = 0; c < CDIM; c++) {
            h_sh[c * NPAD + n] = acc[c];
            p = fmaf(1.5f * a4[c], acc[c], p);   // 0.6*a_c = 1.5 * (0.4*a_c)
        }
        p_sh[n] = p;
    }
    __syncthreads();

    int n0 = chunk * RPC;

    // Row-paired attention: each warp handles 2 rows/iter; h_sh[m] loads shared.
    for (int g = warp; g < NGRP; g += 8) {
        int  r0 = n0 + 2 * g;
        bool v1 = (2 * g + 1) < RPC;
        int  r1 = v1 ? r0 + 1 : r0;

        float hn0[CDIM], hn1[CDIM];
#pragma unroll
        for (int c = 0; c < CDIM; c++) {
            hn0[c] = h_sh[c * NPAD + r0];
            hn1[c] = h_sh[c * NPAD + r1];
        }
        float pn0 = p_sh[r0], pn1 = p_sh[r1];

        float e0[NWORDS], e1[NWORDS];
#pragma unroll
        for (int k = 0; k < NWORDS; k++) {
            int m  = k * 32 + lane;
            int mm = min(m, NN - 1);
            float pm = p_sh[mm];
            float s00 = 0.f, s01 = 0.f, s10 = 0.f, s11 = 0.f;
#pragma unroll
            for (int c = 0; c < CDIM; c++) {
                float hm = h_sh[c * NPAD + mm];
                float x0 = hn0[c] + hm;
                float x1 = hn1[c] + hm;
                if (c & 1) { s01 = fmaf(a4[c], fabsf(x0), s01);
                             s11 = fmaf(a4[c], fabsf(x1), s11); }
                else       { s00 = fmaf(a4[c], fabsf(x0), s00);
                             s10 = fmaf(a4[c], fabsf(x1), s10); }
            }
            bool inb = (m < NN);
            float av0 = inb ? __ldg(&A[r0 * NN + m]) : 0.0f;
            float av1 = inb ? __ldg(&A[r1 * NN + m]) : 0.0f;
            e0[k] = (av0 > 0.0f) ? (pn0 + pm + (s00 + s01)) : NEG;
            e1[k] = (av1 > 0.0f) ? (pn1 + pm + (s10 + s11)) : NEG;
        }

        // row max
        float mx0 = e0[0], mx1 = e1[0];
#pragma unroll
        for (int k = 1; k < NWORDS; k++) {
            mx0 = fmaxf(mx0, e0[k]);
            mx1 = fmaxf(mx1, e1[k]);
        }
#pragma unroll
        for (int off = 16; off; off >>= 1) {
            mx0 = fmaxf(mx0, __shfl_xor_sync(0xffffffffu, mx0, off));
            mx1 = fmaxf(mx1, __shfl_xor_sync(0xffffffffu, mx1, off));
        }

        // softmax normalizer
        float s0 = 0.f, s1 = 0.f;
#pragma unroll
        for (int k = 0; k < NWORDS; k++) {
            s0 += __expf(e0[k] - mx0);
            s1 += __expf(e1[k] - mx1);
        }
#pragma unroll
        for (int off = 16; off; off >>= 1) {
            s0 += __shfl_xor_sync(0xffffffffu, s0, off);
            s1 += __shfl_xor_sync(0xffffffffu, s1, off);
        }

        // diagonal score: pull e[r,r] from the lane/word that computed it
        int kd0 = r0 >> 5, ld0 = r0 & 31;
        int kd1 = r1 >> 5, ld1 = r1 & 31;
        float d0 = NEG, d1 = NEG;
#pragma unroll
        for (int k = 0; k < NWORDS; k++) {
            if (k == kd0) d0 = e0[k];
            if (k == kd1) d1 = e1[k];
        }
        d0 = __shfl_sync(0xffffffffu, d0, ld0);
        d1 = __shfl_sync(0xffffffffu, d1, ld1);
        float att0 = __fdividef(__expf(d0 - mx0), s0);
        float att1 = __fdividef(__expf(d1 - mx1), s1);

        // out[b][n][t][hd*8+c] = att_diag * h
        if (lane < CDIM) {
            out[((size_t)(b * NN + r0) * TT + t) * (HH * CDIM) + hd * CDIM + lane]
                = att0 * h_sh[lane * NPAD + r0];
            if (v1)
                out[((size_t)(b * NN + r1) * TT + t) * (HH * CDIM) + hd * CDIM + lane]
                    = att1 * h_sh[lane * NPAD + r1];
        }
    }
}

// ---------------------------------------------------------------------------
extern "C" void kernel_launch(void* const* d_in, const int* in_sizes, int n_in,
                              void* d_out, int out_size) {
    const float* X  = (const float*)d_in[0];   // (2,207,12,64)
    const float* A  = (const float*)d_in[1];   // (207,207)
    const float* W  = (const float*)d_in[2];   // (64,64)
    const float* av = (const float*)d_in[3];   // (8,)
    float* out = (float*)d_out;                // (2,207,12,64)

    k_fused<<<BB * TT * HH * NCHUNK, 256>>>(X, A, W, av, out);
}